// round 2
// baseline (speedup 1.0000x reference)
#include <cuda_runtime.h>
#include <cuda_bf16.h>
#include <math.h>

#define BATCH    512
#define FDIM     128
#define KNEG     4096
#define NDATA    1200000
#define INV_TEMP (1.0f/0.07f)
#define EPSN     1e-12f
#define SLOTS    16
#define SPILL_CAP 8192

// scratch (device globals; no runtime allocation allowed)
__device__ float          g_s[BATCH * FDIM];     // normalized student fp32
__device__ __nv_bfloat16  g_sb[BATCH * FDIM];    // normalized student bf16 (L1-resident)
__device__ float          g_t[BATCH * FDIM];     // normalized teacher
__device__ float          g_pos[BATCH];          // positive logits
__device__ float          g_sumexp[BATCH];       // sum exp(logit - M), M = 1/TEMP
__device__ unsigned int   g_count[NDATA];        // refs per bank row
__device__ unsigned short g_table[(size_t)NDATA * SLOTS]; // batch ids per row
__device__ unsigned int   g_spill[SPILL_CAP];    // packed (n<<9)|b overflow
__device__ unsigned int   g_nspill;

__device__ __forceinline__ float warpSum(float v) {
#pragma unroll
    for (int o = 16; o > 0; o >>= 1) v += __shfl_xor_sync(0xffffffffu, v, o);
    return v;
}

__device__ __forceinline__ float blockSum128(float v, float* sh) {
    int w = threadIdx.x >> 5, l = threadIdx.x & 31;
    v = warpSum(v);
    if (l == 0) sh[w] = v;
    __syncthreads();
    float t = sh[0] + sh[1] + sh[2] + sh[3];
    __syncthreads();
    return t;
}

// ---------------------------------------------------------------------------
// 0) reset per-launch state (graph-replay safe)
__global__ void clear_kernel() {
    unsigned i = blockIdx.x * blockDim.x + threadIdx.x;
    if (i < NDATA / 4)
        reinterpret_cast<uint4*>(g_count)[i] = make_uint4(0, 0, 0, 0);
    if (i == 0) g_nspill = 0;
}

// ---------------------------------------------------------------------------
// 1) normalize s/t, pos logits, init sumexp with positive term, emit bf16 s
__global__ void prep_kernel(const float* __restrict__ stu,
                            const float* __restrict__ tea) {
    __shared__ float sh[4];
    int b = blockIdx.x, d = threadIdx.x;
    float sv = stu[b * FDIM + d];
    float tv = tea[b * FDIM + d];
    float sn2 = blockSum128(sv * sv, sh);
    float tn2 = blockSum128(tv * tv, sh);
    float sn = sv / fmaxf(sqrtf(sn2), EPSN);
    float tn = tv / fmaxf(sqrtf(tn2), EPSN);
    g_s[b * FDIM + d] = sn;
    g_sb[b * FDIM + d] = __float2bfloat16(sn);
    g_t[b * FDIM + d] = tn;
    float pos = blockSum128(sn * tn, sh) * INV_TEMP;
    if (d == 0) {
        g_pos[b] = pos;
        g_sumexp[b] = __expf(pos - INV_TEMP);
    }
}

// ---------------------------------------------------------------------------
// 2) build inverted index: row n -> list of batch ids (slot reserve by atomic)
__global__ void build_kernel(const int* __restrict__ r,
                             const int* __restrict__ idxs) {
    int gid = blockIdx.x * blockDim.x + threadIdx.x;   // exactly BATCH*KNEG threads
    int b = gid >> 12;
    int rv = __ldg(&r[gid]);
    int self = __ldg(&idxs[b]);
    int n = rv + (rv >= self);
    unsigned c = atomicAdd(&g_count[n], 1u);
    if (c < SLOTS) {
        g_table[(size_t)n * SLOTS + c] = (unsigned short)b;
    } else {
        unsigned p = atomicAdd(&g_nspill, 1u);
        if (p < SPILL_CAP) g_spill[p] = ((unsigned)n << 9) | (unsigned)b;
    }
}

// ---------------------------------------------------------------------------
// 3) FUSED: stream bank once -> copy to out (+1 float shift) AND compute all
// negative dots for rows referenced by the inverted index.
__global__ __launch_bounds__(256)
void fused_kernel(const float* __restrict__ bank, float* __restrict__ out) {
    int lane = threadIdx.x & 31;
    int warp = (blockIdx.x * blockDim.x + threadIdx.x) >> 5;
    int nwarps = (gridDim.x * blockDim.x) >> 5;

    for (int n = warp; n < NDATA; n += nwarps) {
        const float4* rp = reinterpret_cast<const float4*>(bank + (size_t)n * FDIM);
        float4 v = __ldcs(rp + lane);          // evict-first: keep L1 for g_sb

        // ---- shifted store: out float index = 1 + n*128 + d ----
        // aligned float4 at d = 3+4l needs {row[3+4l]} = my v.w and next lane's v.x,v.y,v.z
        float nx = __shfl_down_sync(0xffffffffu, v.x, 1);
        float ny = __shfl_down_sync(0xffffffffu, v.y, 1);
        float nz = __shfl_down_sync(0xffffffffu, v.z, 1);
        float* ob = out + 1 + (size_t)n * FDIM;
        if (lane < 31)
            *reinterpret_cast<float4*>(ob + 3 + 4 * lane) = make_float4(v.w, nx, ny, nz);
        if (lane == 0) {
            ob[0] = v.x;
            *reinterpret_cast<float2*>(ob + 1) = make_float2(v.y, v.z);  // 8B aligned
        }
        if (lane == 31) ob[127] = v.w;

        // ---- negative logits for refs of this row ----
        unsigned cnt = 0;
        if (lane == 0) cnt = __ldg(&g_count[n]);
        cnt = __shfl_sync(0xffffffffu, cnt, 0);
        if (cnt) {
            float q = fmaf(v.x, v.x, fmaf(v.y, v.y, fmaf(v.z, v.z, v.w * v.w)));
            q = warpSum(q);
            float rq = rsqrtf(fmaxf(q, 1e-24f)) * INV_TEMP;
            unsigned cc = cnt < (unsigned)SLOTS ? cnt : (unsigned)SLOTS;
            int tb = 0;
            if (lane < (int)cc) tb = g_table[(size_t)n * SLOTS + lane];
            for (unsigned i = 0; i < cc; i++) {
                int b = __shfl_sync(0xffffffffu, tb, i);
                uint2 sw = *reinterpret_cast<const uint2*>(&g_sb[b * FDIM + 4 * lane]);
                float2 f01 = __bfloat1622float2(*reinterpret_cast<__nv_bfloat162*>(&sw.x));
                float2 f23 = __bfloat1622float2(*reinterpret_cast<__nv_bfloat162*>(&sw.y));
                float d = fmaf(v.x, f01.x, fmaf(v.y, f01.y, fmaf(v.z, f23.x, v.w * f23.y)));
                d = warpSum(d);
                if (lane == 0) atomicAdd(&g_sumexp[b], __expf(fmaf(d, rq, -INV_TEMP)));
            }
        }
    }
}

// ---------------------------------------------------------------------------
// 4) spill cleanup (normally 0 entries) — direct gather for overflow refs
__global__ void spill_kernel(const float* __restrict__ bank) {
    unsigned ns = g_nspill;
    if (ns > SPILL_CAP) ns = SPILL_CAP;
    int lane = threadIdx.x & 31;
    int warp = threadIdx.x >> 5;
    for (unsigned e = warp; e < ns; e += 8) {
        unsigned p = g_spill[e];
        int n = p >> 9, b = p & 511;
        float4 v = *(reinterpret_cast<const float4*>(bank + (size_t)n * FDIM) + lane);
        float q = warpSum(fmaf(v.x, v.x, fmaf(v.y, v.y, fmaf(v.z, v.z, v.w * v.w))));
        float4 s4 = *reinterpret_cast<const float4*>(&g_s[b * FDIM + 4 * lane]);
        float d = warpSum(fmaf(v.x, s4.x, fmaf(v.y, s4.y, fmaf(v.z, s4.z, v.w * s4.w))));
        float l = d * rsqrtf(fmaxf(q, 1e-24f)) * INV_TEMP;
        if (lane == 0) atomicAdd(&g_sumexp[b], __expf(l - INV_TEMP));
    }
}

// ---------------------------------------------------------------------------
// 5) EMA update + l2norm + scatter (last duplicate wins, like JAX .set)
__global__ void scatter_kernel(const float* __restrict__ bank,
                               const int* __restrict__ idxs,
                               float* __restrict__ outBank) {
    __shared__ float sh[4];
    __shared__ int skip;
    int b = blockIdx.x, d = threadIdx.x;
    int idx = idxs[b];
    if (d == 0) {
        int s = 0;
        for (int bb = b + 1; bb < BATCH; bb++)
            if (idxs[bb] == idx) { s = 1; break; }
        skip = s;
    }
    float u = 0.5f * bank[(size_t)idx * FDIM + d] + 0.5f * g_t[b * FDIM + d];
    float n2 = blockSum128(u * u, sh);   // has syncthreads -> skip visible
    if (!skip)
        outBank[(size_t)idx * FDIM + d] = u / fmaxf(sqrtf(n2), EPSN);
}

// ---------------------------------------------------------------------------
// 6) loss = mean( M + log(sumexp_b) - pos_b )
__global__ void finalize_kernel(float* __restrict__ out) {
    __shared__ float sh[16];
    int tid = threadIdx.x;            // 512 threads
    float v = INV_TEMP + logf(g_sumexp[tid]) - g_pos[tid];
    v = warpSum(v);
    if ((tid & 31) == 0) sh[tid >> 5] = v;
    __syncthreads();
    if (tid == 0) {
        float tot = 0.0f;
#pragma unroll
        for (int w = 0; w < 16; w++) tot += sh[w];
        out[0] = tot * (1.0f / BATCH);
    }
}

// ---------------------------------------------------------------------------
extern "C" void kernel_launch(void* const* d_in, const int* in_sizes, int n_in,
                              void* d_out, int out_size) {
    const float* stu  = (const float*)d_in[0];
    const float* tea  = (const float*)d_in[1];
    const float* bank = (const float*)d_in[2];
    const int*   idxs = (const int*)d_in[3];
    const int*   r    = (const int*)d_in[4];
    float* out = (float*)d_out;

    clear_kernel<<<(NDATA / 4 + 255) / 256, 256>>>();
    prep_kernel<<<BATCH, 128>>>(stu, tea);
    build_kernel<<<(BATCH * KNEG) / 256, 256>>>(r, idxs);
    fused_kernel<<<4096, 256>>>(bank, out);
    spill_kernel<<<1, 256>>>(bank);
    scatter_kernel<<<BATCH, 128>>>(bank, idxs, out + 1);
    finalize_kernel<<<1, 512>>>(out);
}